// round 10
// baseline (speedup 1.0000x reference)
#include <cuda_runtime.h>

#define B_ 128
#define T_ 1024
#define N_ 64

// Per-batch losses + completion counter; reduced by the last-arriving block.
__device__ float g_loss[B_];
__device__ unsigned g_count = 0;   // wraps to 0 every launch via atomicInc(.,B_-1)

typedef unsigned long long u64;

__device__ __forceinline__ u64 pack2(float lo, float hi) {
    u64 d;
    asm("mov.b64 %0, {%1, %2};" : "=l"(d)
        : "r"(__float_as_uint(lo)), "r"(__float_as_uint(hi)));
    return d;
}
__device__ __forceinline__ float unpack_sum(u64 v) {
    unsigned a, b;
    asm("mov.b64 {%0, %1}, %2;" : "=r"(a), "=r"(b) : "l"(v));
    return __uint_as_float(a) + __uint_as_float(b);
}
__device__ __forceinline__ u64 ffma2(u64 a, u64 b, u64 c) {
    u64 d;
    asm("fma.rn.f32x2 %0, %1, %2, %3;" : "=l"(d) : "l"(a), "l"(b), "l"(c));
    return d;
}
__device__ __forceinline__ u64 fadd2(u64 a, u64 b) {
    u64 d;
    asm("add.rn.f32x2 %0, %1, %2;" : "=l"(d) : "l"(a), "l"(b));
    return d;
}

// Full 64-MAC dot: 16x LDS.128 (broadcast) + 32x FFMA2, 8 accumulators.
__device__ __forceinline__ float dot64(const float* __restrict__ rd,
                                       const u64* __restrict__ Ec) {
    const ulonglong2* a4 = (const ulonglong2*)rd;
    u64 acc[8];
#pragma unroll
    for (int m = 0; m < 8; ++m) acc[m] = 0ull;
#pragma unroll
    for (int k = 0; k < 16; ++k) {
        ulonglong2 v = a4[k];
        acc[(2 * k)     & 7] = ffma2(v.x, Ec[2 * k],     acc[(2 * k)     & 7]);
        acc[(2 * k + 1) & 7] = ffma2(v.y, Ec[2 * k + 1], acc[(2 * k + 1) & 7]);
    }
    acc[0] = fadd2(acc[0], acc[1]);
    acc[2] = fadd2(acc[2], acc[3]);
    acc[4] = fadd2(acc[4], acc[5]);
    acc[6] = fadd2(acc[6], acc[7]);
    acc[0] = fadd2(acc[0], acc[2]);
    acc[4] = fadd2(acc[4], acc[6]);
    acc[0] = fadd2(acc[0], acc[4]);
    return unpack_sum(acc[0]);
}

// Main-loop step: branch-free, clamp-free prefetch (pure pointer walk),
// per-group named barrier. RENORM is compile-time.
#define STEP(SRC, DST, RENORM)                                           \
    {                                                                    \
        float p_pref = *pptr;                                            \
        pptr += pstr;                                                    \
        float mult = __expf(p_cur);                                      \
        if (RENORM) {                                                    \
            float a0 = (SRC)[0];                                         \
            mult *= __fdividef(1.0f, a0);                                \
            cacc += __logf(a0);                                          \
        }                                                                \
        float s = dot64((SRC), Ec);                                      \
        my_v = s * mult;                                                 \
        (DST)[j] = my_v;                                                 \
        asm volatile("bar.sync %0, 64;" :: "r"(barid) : "memory");       \
        p_cur = p_nxt;                                                   \
        p_nxt = p_pref;                                                  \
    }

// 128 threads: warps 0-1 FORWARD half-chain, warps 2-3 BACKWARD half-chain,
// meeting at m = ceil(L/2): Z = sum_j alpha_m[j] * w_m[j]. Last-arriving
// block reduces g_loss into out (finalize kernel folded in).
// Renormalization every 4 steps (every 8 overflows fp32 -- verified R9).
__global__ void __launch_bounds__(2 * N_, 1) crf_forward_kernel(
    const float* __restrict__ pot,     // (B,T,N)
    const int*   __restrict__ tags,    // (B,T)
    const int*   __restrict__ seqlen,  // (B,)
    const float* __restrict__ ck,      // (N,N)
    const float* __restrict__ sw,      // (B,)
    float*       __restrict__ out)     // (1,)
{
    const int tid = threadIdx.x;
    const int b   = blockIdx.x;
    const int grp = tid >> 6;          // 0 = forward, 1 = backward
    const int j   = tid & (N_ - 1);
    const int len = seqlen[b];
    const int L   = len - 1;           // len >= T/2 = 512
    const int barid = 1 + grp;

    __shared__ __align__(16) float buf[2][2][N_];  // [grp][parity][state]
    __shared__ float red2[2 * N_];
    __shared__ float c_share;
    __shared__ int   is_last;

    // E registers: forward = column j of exp(ck); backward = row j.
    u64 Ec[N_ / 2];
    if (grp == 0) {
#pragma unroll
        for (int i = 0; i < N_ / 2; ++i)
            Ec[i] = pack2(__expf(ck[(2 * i) * N_ + j]),
                          __expf(ck[(2 * i + 1) * N_ + j]));
    } else {
#pragma unroll
        for (int i = 0; i < N_ / 2; ++i)
            Ec[i] = pack2(__expf(ck[j * N_ + 2 * i]),
                          __expf(ck[j * N_ + 2 * i + 1]));
    }

    const float* Pb   = pot  + (size_t)b * T_ * N_;
    const int*   tagb = tags + b * T_;

    // ---------------- sequence score ----------------
    float ss = 0.f;
    for (int t = tid; t < len; t += 2 * N_) {
        int tg = tagb[t];
        ss += Pb[t * N_ + tg];
        if (t >= 1) ss += ck[tagb[t - 1] * N_ + tg];
    }
    red2[tid] = ss;
    __syncthreads();
#pragma unroll
    for (int off = N_; off >= 1; off >>= 1) {
        if (tid < off) red2[tid] += red2[tid + off];
        __syncthreads();
    }
    const float seq_score = red2[0];
    __syncthreads();

    const int stepsF = (L + 1) >> 1;   // forward applies t = 1..stepsF
    const int stepsB = L - stepsF;     // backward applies t = L..stepsF+1
    const int niter  = stepsF;

    // ---------------- init ----------------
    float cacc, my_v, p_cur, p_nxt;
    const float* pptr;
    int pstr, pidx;
    if (grp == 0) {
        cacc  = Pb[0];
        my_v  = __expf(Pb[j] - cacc);
        p_cur = Pb[1 * N_ + j];
        p_nxt = Pb[2 * N_ + j];
        pidx  = 3;       pstr = N_;
    } else {
        cacc  = Pb[L * N_];
        my_v  = __expf(Pb[L * N_ + j] - cacc);
        p_cur = Pb[(L - 1) * N_ + j];
        p_nxt = Pb[(L - 2) * N_ + j];
        pidx  = L - 3;   pstr = -N_;
    }
    pptr = Pb + pidx * N_ + j;
    float* b0 = &buf[grp][0][0];
    float* b1 = &buf[grp][1][0];
    b0[j] = my_v;
    asm volatile("bar.sync %0, 64;" :: "r"(barid) : "memory");

    // ---------------- main loop: uniform, unrolled x8, renorm every 4 ------
    // For i < nmain: backward strictly active, not last_active; prefetch
    // indices provably stay in [0, L] -> no clamping needed.
    const int nmain = (niter >= 3) ? ((niter - 2) & ~7) : 0;
    for (int i = 0; i < nmain; i += 8) {
        STEP(b0, b1, true)
        STEP(b1, b0, false)
        STEP(b0, b1, false)
        STEP(b1, b0, false)
        STEP(b0, b1, true)
        STEP(b1, b0, false)
        STEP(b0, b1, false)
        STEP(b1, b0, false)
    }
    pidx += (grp == 0) ? nmain : -nmain;

    // ---------------- tail (2..9 iters, predicated, clamped) ----------------
    int cur = 0;
    for (int i = nmain; i < niter; ++i) {
        float* src = cur ? b1 : b0;
        float* dst = cur ? b0 : b1;
        const bool active      = (grp == 0) || (i < stepsB);
        const bool last_active = (grp == 1) && (i == stepsB - 1);
        float p_pref = Pb[max(min(pidx, L), 0) * N_ + j];
        pidx += (grp == 0) ? 1 : -1;
        float mult = last_active ? 1.0f : __expf(p_cur);
        if (((i & 3) == 0) && active) {
            float a0 = src[0];
            mult *= __fdividef(1.0f, a0);
            cacc += __logf(a0);
        }
        float s = dot64(src, Ec);
        if (active) my_v = s * mult;
        dst[j] = my_v;
        asm volatile("bar.sync %0, 64;" :: "r"(barid) : "memory");
        p_cur = p_nxt;
        p_nxt = p_pref;
        cur ^= 1;
    }

    // ---------------- combine: Z = sum_j alpha_m[j] * w_m[j] ----------------
    if (tid == N_) c_share = cacc;            // backward group's log-offset
    __syncthreads();
    if (grp == 0) red2[j] = buf[0][cur][j] * buf[1][cur][j];
    __syncthreads();
#pragma unroll
    for (int off = N_ / 2; off >= 1; off >>= 1) {
        if (tid < off) red2[tid] += red2[tid + off];
        __syncthreads();
    }

    if (tid == 0) {
        float log_norm = cacc + c_share + logf(red2[0]);
        g_loss[b] = -(seq_score - log_norm) * sw[b];
        __threadfence();
        unsigned old = atomicInc(&g_count, B_ - 1);   // wraps -> self-resetting
        is_last = (old == B_ - 1);
    }
    __syncthreads();

    // ---------------- last block reduces all losses ----------------
    if (is_last) {
        volatile float* gl = g_loss;      // bypass L1 (other SMs' writes)
        red2[tid] = gl[tid];              // 128 threads == B_ entries
        __syncthreads();
#pragma unroll
        for (int off = N_; off >= 1; off >>= 1) {
            if (tid < off) red2[tid] += red2[tid + off];
            __syncthreads();
        }
        if (tid == 0) out[0] = red2[0] * (1.0f / (float)B_);
    }
}

extern "C" void kernel_launch(void* const* d_in, const int* in_sizes, int n_in,
                              void* d_out, int out_size)
{
    const float* pot    = (const float*)d_in[0];
    const int*   tags   = (const int*)  d_in[1];
    const int*   seqlen = (const int*)  d_in[2];
    const float* ck     = (const float*)d_in[3];
    const float* sw     = (const float*)d_in[4];

    crf_forward_kernel<<<B_, 2 * N_>>>(pot, tags, seqlen, ck, sw, (float*)d_out);
}

// round 11
// speedup vs baseline: 1.1440x; 1.1440x over previous
#include <cuda_runtime.h>

#define B_ 128
#define T_ 1024
#define N_ 64

// Per-batch losses + completion counter; reduced by the last-arriving block.
__device__ float g_loss[B_];
__device__ unsigned g_count = 0;   // wraps to 0 every launch via atomicInc(.,B_-1)

typedef unsigned long long u64;

__device__ __forceinline__ u64 pack2(float lo, float hi) {
    u64 d;
    asm("mov.b64 %0, {%1, %2};" : "=l"(d)
        : "r"(__float_as_uint(lo)), "r"(__float_as_uint(hi)));
    return d;
}
__device__ __forceinline__ float unpack_sum(u64 v) {
    unsigned a, b;
    asm("mov.b64 {%0, %1}, %2;" : "=r"(a), "=r"(b) : "l"(v));
    return __uint_as_float(a) + __uint_as_float(b);
}
__device__ __forceinline__ u64 ffma2(u64 a, u64 b, u64 c) {
    u64 d;
    asm("fma.rn.f32x2 %0, %1, %2, %3;" : "=l"(d) : "l"(a), "l"(b), "l"(c));
    return d;
}
__device__ __forceinline__ u64 fadd2(u64 a, u64 b) {
    u64 d;
    asm("add.rn.f32x2 %0, %1, %2;" : "=l"(d) : "l"(a), "l"(b));
    return d;
}

// Full 64-MAC dot: 16x LDS.128 (broadcast) + 32x FFMA2, 8 accumulators.
__device__ __forceinline__ float dot64(const float* __restrict__ rd,
                                       const u64* __restrict__ Ec) {
    const ulonglong2* a4 = (const ulonglong2*)rd;
    u64 acc[8];
#pragma unroll
    for (int m = 0; m < 8; ++m) acc[m] = 0ull;
#pragma unroll
    for (int k = 0; k < 16; ++k) {
        ulonglong2 v = a4[k];
        acc[(2 * k)     & 7] = ffma2(v.x, Ec[2 * k],     acc[(2 * k)     & 7]);
        acc[(2 * k + 1) & 7] = ffma2(v.y, Ec[2 * k + 1], acc[(2 * k + 1) & 7]);
    }
    acc[0] = fadd2(acc[0], acc[1]);
    acc[2] = fadd2(acc[2], acc[3]);
    acc[4] = fadd2(acc[4], acc[5]);
    acc[6] = fadd2(acc[6], acc[7]);
    acc[0] = fadd2(acc[0], acc[2]);
    acc[4] = fadd2(acc[4], acc[6]);
    acc[0] = fadd2(acc[0], acc[4]);
    return unpack_sum(acc[0]);
}

// One scan step, branch-free, group-uniform (R8-validated form).
#define STEP(SRC, DST, RENORM)                                           \
    {                                                                    \
        float p_pref = Pb[max(pidx, 0) * N_ + j];                        \
        pidx += pinc;                                                    \
        float mult = __expf(p_cur);                                      \
        if (RENORM) {                                                    \
            float a0 = (SRC)[0];                                         \
            mult *= __fdividef(1.0f, a0);                                \
            cacc += __logf(a0);                                          \
        }                                                                \
        float s = dot64((SRC), Ec);                                      \
        my_v = s * mult;                                                 \
        (DST)[j] = my_v;                                                 \
        asm volatile("bar.sync %0, 64;" :: "r"(barid) : "memory");       \
        p_cur = p_nxt;                                                   \
        p_nxt = p_pref;                                                  \
    }

// 128 threads: warps 0-1 FORWARD half-chain, warps 2-3 BACKWARD half-chain,
// meeting at m = ceil(L/2): Z = sum_j alpha_m[j] * w_m[j]. Last-arriving
// block reduces g_loss into out (finalize kernel folded in).
__global__ void __launch_bounds__(2 * N_, 1) crf_forward_kernel(
    const float* __restrict__ pot,     // (B,T,N)
    const int*   __restrict__ tags,    // (B,T)
    const int*   __restrict__ seqlen,  // (B,)
    const float* __restrict__ ck,      // (N,N)
    const float* __restrict__ sw,      // (B,)
    float*       __restrict__ out)     // (1,)
{
    const int tid = threadIdx.x;
    const int b   = blockIdx.x;
    const int grp = tid >> 6;          // 0 = forward, 1 = backward
    const int j   = tid & (N_ - 1);
    const int len = seqlen[b];
    const int L   = len - 1;           // len >= T/2 = 512
    const int barid = 1 + grp;

    __shared__ __align__(16) float buf[2][2][N_];  // [grp][parity][state]
    __shared__ float red2[2 * N_];
    __shared__ float c_share;
    __shared__ int   is_last;

    // E registers: forward = column j of exp(ck); backward = row j.
    u64 Ec[N_ / 2];
    if (grp == 0) {
#pragma unroll
        for (int i = 0; i < N_ / 2; ++i)
            Ec[i] = pack2(__expf(ck[(2 * i) * N_ + j]),
                          __expf(ck[(2 * i + 1) * N_ + j]));
    } else {
#pragma unroll
        for (int i = 0; i < N_ / 2; ++i)
            Ec[i] = pack2(__expf(ck[j * N_ + 2 * i]),
                          __expf(ck[j * N_ + 2 * i + 1]));
    }

    const float* Pb   = pot  + (size_t)b * T_ * N_;
    const int*   tagb = tags + b * T_;

    // ---------------- sequence score ----------------
    float ss = 0.f;
    for (int t = tid; t < len; t += 2 * N_) {
        int tg = tagb[t];
        ss += Pb[t * N_ + tg];
        if (t >= 1) ss += ck[tagb[t - 1] * N_ + tg];
    }
    red2[tid] = ss;
    __syncthreads();
#pragma unroll
    for (int off = N_; off >= 1; off >>= 1) {
        if (tid < off) red2[tid] += red2[tid + off];
        __syncthreads();
    }
    const float seq_score = red2[0];
    __syncthreads();

    const int stepsF = (L + 1) >> 1;   // forward applies t = 1..stepsF
    const int stepsB = L - stepsF;     // backward applies t = L..stepsF+1
    const int niter  = stepsF;

    // ---------------- init ----------------
    float cacc, my_v, p_cur, p_nxt;
    int pidx, pinc;
    if (grp == 0) {
        cacc  = Pb[0];
        my_v  = __expf(Pb[j] - cacc);
        p_cur = Pb[1 * N_ + j];
        p_nxt = Pb[2 * N_ + j];
        pidx  = 3;   pinc = 1;
    } else {
        cacc  = Pb[L * N_];
        my_v  = __expf(Pb[L * N_ + j] - cacc);
        p_cur = Pb[(L - 1) * N_ + j];
        p_nxt = Pb[(L - 2) * N_ + j];
        pidx  = L - 3;   pinc = -1;
    }
    float* b0 = &buf[grp][0][0];
    float* b1 = &buf[grp][1][0];
    b0[j] = my_v;
    asm volatile("bar.sync %0, 64;" :: "r"(barid) : "memory");

    // ---------------- main loop: uniform, unrolled x4, renorm every 4 ------
    const int nmain = (niter >= 3) ? ((niter - 2) & ~3) : 0;
    for (int i = 0; i < nmain; i += 4) {
        STEP(b0, b1, true)
        STEP(b1, b0, false)
        STEP(b0, b1, false)
        STEP(b1, b0, false)
    }

    // ---------------- tail (2..5 iters, predicated) ----------------
    int cur = 0;
    for (int i = nmain; i < niter; ++i) {
        float* src = cur ? b1 : b0;
        float* dst = cur ? b0 : b1;
        const bool active      = (grp == 0) || (i < stepsB);
        const bool last_active = (grp == 1) && (i == stepsB - 1);
        float p_pref = Pb[max(pidx, 0) * N_ + j];
        pidx += pinc;
        float mult = last_active ? 1.0f : __expf(p_cur);
        if (((i & 3) == 0) && active) {
            float a0 = src[0];
            mult *= __fdividef(1.0f, a0);
            cacc += __logf(a0);
        }
        float s = dot64(src, Ec);
        if (active) my_v = s * mult;
        dst[j] = my_v;
        asm volatile("bar.sync %0, 64;" :: "r"(barid) : "memory");
        p_cur = p_nxt;
        p_nxt = p_pref;
        cur ^= 1;
    }

    // ---------------- combine: Z = sum_j alpha_m[j] * w_m[j] ----------------
    if (tid == N_) c_share = cacc;            // backward group's log-offset
    __syncthreads();
    if (grp == 0) red2[j] = buf[0][cur][j] * buf[1][cur][j];
    __syncthreads();
#pragma unroll
    for (int off = N_ / 2; off >= 1; off >>= 1) {
        if (tid < off) red2[tid] += red2[tid + off];
        __syncthreads();
    }

    if (tid == 0) {
        float log_norm = cacc + c_share + logf(red2[0]);
        g_loss[b] = -(seq_score - log_norm) * sw[b];
        __threadfence();
        unsigned old = atomicInc(&g_count, B_ - 1);   // wraps -> self-resetting
        is_last = (old == B_ - 1);
    }
    __syncthreads();

    // ---------------- last block reduces all losses ----------------
    if (is_last) {
        volatile float* gl = g_loss;      // bypass L1 (other SMs' writes)
        red2[tid] = gl[tid];              // 128 threads == B_ entries
        __syncthreads();
#pragma unroll
        for (int off = N_; off >= 1; off >>= 1) {
            if (tid < off) red2[tid] += red2[tid + off];
            __syncthreads();
        }
        if (tid == 0) out[0] = red2[0] * (1.0f / (float)B_);
    }
}

extern "C" void kernel_launch(void* const* d_in, const int* in_sizes, int n_in,
                              void* d_out, int out_size)
{
    const float* pot    = (const float*)d_in[0];
    const int*   tags   = (const int*)  d_in[1];
    const int*   seqlen = (const int*)  d_in[2];
    const float* ck     = (const float*)d_in[3];
    const float* sw     = (const float*)d_in[4];

    crf_forward_kernel<<<B_, 2 * N_>>>(pot, tags, seqlen, ck, sw, (float*)d_out);
}